// round 3
// baseline (speedup 1.0000x reference)
#include <cuda_runtime.h>
#include <cuda_bf16.h>
#include <math.h>

#define NN   30000
#define EE   120000
#define N2   15000
#define N3   7500
#define GG   512
#define YW   1664   // 26*64 (25 hidden rows + 1 bias row)

typedef unsigned long long ull;

#define FMA2(d, a, b, c) \
    asm("fma.rn.f32x2 %0, %1, %2, %3;" : "=l"(d) : "l"(a), "l"(b), "l"(c))

__device__ __forceinline__ ull pack_dup(float v) {
    ull p; unsigned int u = __float_as_uint(v);
    asm("mov.b64 %0, {%1, %1};" : "=l"(p) : "r"(u));
    return p;
}

// ---------------- scratch (static device allocations) ----------------
__device__ float d_acc1[NN * 32];
__device__ int   d_cnt1[NN];
__device__ float d_x2[N2 * 32];
__device__ float d_pos2[N2 * 2];
__device__ float d_cart[EE * 2];
__device__ int   d_maxbits;
__device__ float d_y[(size_t)N2 * YW];
__device__ float d_acc2[N2 * 64];
__device__ int   d_cnt2[N2];
__device__ float d_gsum[GG * 64];
__device__ int   d_gcnt[GG];
// CSR (edges grouped by layer-2 source node r2)
__device__ int   d_deg[N2];
__device__ int   d_off[N2];
__device__ int   d_cursor[N2];
__device__ int   d_edst[EE];        // destination c2 per CSR slot
__device__ float d_hid[(size_t)EE * 25];    // relu MLP hidden per CSR slot

__device__ __forceinline__ float eluf(float x) { return x > 0.f ? x : expm1f(x); }

// ---------------- K0: zero accumulators ----------------
__global__ void k_zero() {
    int i = blockIdx.x * blockDim.x + threadIdx.x;
    int stride = gridDim.x * blockDim.x;
    for (int j = i; j < NN * 32; j += stride) d_acc1[j] = 0.f;
    for (int j = i; j < N2 * 64; j += stride) d_acc2[j] = 0.f;
    for (int j = i; j < NN; j += stride) d_cnt1[j] = 0;
    for (int j = i; j < N2; j += stride) { d_cnt2[j] = 0; d_deg[j] = 0; d_cursor[j] = 0; }
    for (int j = i; j < GG * 64; j += stride) d_gsum[j] = 0.f;
    for (int j = i; j < GG; j += stride) d_gcnt[j] = 0;
    if (i == 0) d_maxbits = 0;
}

// ---------------- K1: layer-1 edge kernel (warp per edge) ----------------
__global__ void k_edge1(const float* __restrict__ x, const float* __restrict__ ea,
                        const float* __restrict__ w1a, const float* __restrict__ b1a,
                        const float* __restrict__ w1b, const float* __restrict__ b1b,
                        const int* __restrict__ ei) {
    int warp = (blockIdx.x * blockDim.x + threadIdx.x) >> 5;
    int lane = threadIdx.x & 31;
    if (warp >= EE) return;
    int src = ei[warp];
    int dst = ei[EE + warp];
    float e0 = __ldg(ea + warp * 2);
    float e1 = __ldg(ea + warp * 2 + 1);
    float hid[25];
#pragma unroll
    for (int h = 0; h < 25; h++) {
        float v = fmaf(e0, __ldg(w1a + h), fmaf(e1, __ldg(w1a + 25 + h), __ldg(b1a + h)));
        hid[h] = fmaxf(v, 0.f);
    }
    float s = __ldg(b1b + lane);
#pragma unroll
    for (int h = 0; h < 25; h++)
        s = fmaf(hid[h], __ldg(w1b + h * 32 + lane), s);
    float xs = __ldg(x + src);
    atomicAdd(d_acc1 + dst * 32 + lane, xs * s);
    if (lane == 0) atomicAdd(d_cnt1 + dst, 1);
}

// ---------------- K2: fused layer-1 node update + pairwise max pool + pos mean ----------------
__global__ void k_node1pool(const float* __restrict__ x, const float* __restrict__ root1,
                            const float* __restrict__ bias1, const float* __restrict__ pos) {
    int idx = blockIdx.x * blockDim.x + threadIdx.x;
    if (idx >= N2 * 32) return;
    int p = idx >> 5, o = idx & 31;
    float v[2];
#pragma unroll
    for (int j = 0; j < 2; j++) {
        int n = 2 * p + j;
        float c = fmaxf((float)d_cnt1[n], 1.f);
        float t = d_acc1[n * 32 + o] / c + __ldg(x + n) * __ldg(root1 + o) + __ldg(bias1 + o);
        v[j] = eluf(t);
    }
    d_x2[idx] = fmaxf(v[0], v[1]);
    if (o < 2)
        d_pos2[p * 2 + o] = 0.5f * (pos[(2 * p) * 2 + o] + pos[(2 * p + 1) * 2 + o]);
}

// ---------------- K3 (side stream): edge geometry + abs-max + CSR degree + cnt2 ----------------
__global__ void k_geom(const int* __restrict__ ei) {
    int t = blockIdx.x * blockDim.x + threadIdx.x;
    float m = 0.f;
    if (t < EE) {
        int r2 = ei[t] >> 1, c2 = ei[EE + t] >> 1;
        float cx = 0.f, cy = 0.f;
        if (r2 != c2) {
            cx = d_pos2[c2 * 2]     - d_pos2[r2 * 2];
            cy = d_pos2[c2 * 2 + 1] - d_pos2[r2 * 2 + 1];
            atomicAdd(&d_deg[r2], 1);
            atomicAdd(&d_cnt2[c2], 1);
        }
        d_cart[t * 2] = cx;
        d_cart[t * 2 + 1] = cy;
        m = fmaxf(fabsf(cx), fabsf(cy));
    }
#pragma unroll
    for (int off = 16; off > 0; off >>= 1)
        m = fmaxf(m, __shfl_down_sync(0xffffffffu, m, off));
    if ((threadIdx.x & 31) == 0)
        atomicMax(&d_maxbits, __float_as_int(m)); // nonneg floats: int order == float order
}

// ---------------- K4 (side stream): exclusive scan of degrees (single block) ----------------
__global__ void k_scan() {
    const int T = 1024;
    const int CH = (N2 + T - 1) / T;  // 15
    __shared__ int partial[T];
    int t = threadIdx.x;
    int base = t * CH;
    int local[CH];
    int s = 0;
#pragma unroll
    for (int i = 0; i < CH; i++) {
        int idx = base + i;
        int v = (idx < N2) ? d_deg[idx] : 0;
        local[i] = s;
        s += v;
    }
    partial[t] = s;
    __syncthreads();
    for (int d = 1; d < T; d <<= 1) {
        int v = (t >= d) ? partial[t - d] : 0;
        __syncthreads();
        partial[t] += v;
        __syncthreads();
    }
    int offset = (t > 0) ? partial[t - 1] : 0;
#pragma unroll
    for (int i = 0; i < CH; i++) {
        int idx = base + i;
        if (idx < N2) d_off[idx] = offset + local[i];
    }
}

// ---------------- K5 (side stream): CSR fill + per-edge hidden MLP (relu) ----------------
__global__ void k_fill(const int* __restrict__ ei, const float* __restrict__ w2a,
                       const float* __restrict__ b2a) {
    int t = blockIdx.x * blockDim.x + threadIdx.x;
    if (t >= EE) return;
    int r2 = ei[t] >> 1, c2 = ei[EE + t] >> 1;
    if (r2 == c2) return;   // masked: goes to dummy segment, dropped
    int pos = atomicAdd(&d_cursor[r2], 1);
    int slot = d_off[r2] + pos;
    d_edst[slot] = c2;
    float maxv = __int_as_float(d_maxbits);
    float inv = 0.5f / maxv;
    float ea0 = fmaf(d_cart[t * 2],     inv, 0.5f);
    float ea1 = fmaf(d_cart[t * 2 + 1], inv, 0.5f);
    float* hp = d_hid + (size_t)slot * 25;
#pragma unroll
    for (int h = 0; h < 25; h++) {
        float v = fmaf(ea0, __ldg(w2a + h), fmaf(ea1, __ldg(w2a + 25 + h), __ldg(b2a + h)));
        hp[h] = fmaxf(v, 0.f);
    }
}

// ---------------- K6 (main stream, 4th launch): y GEMM with fma.rn.f32x2 ----------------
// y[r, h*64+o] = sum_i x2[r,i]*w2b[h,i*64+o] (h<25);  y[r,25*64+o] = sum_i x2[r,i]*b2b[i*64+o]
// 128x64 tile, K=32, 256 threads; acc packed along m (4 m-pairs x 4 n per thread).
__global__ void __launch_bounds__(256) k_ygemm(const float* __restrict__ w2b,
                                               const float* __restrict__ b2b) {
    __shared__ __align__(16) float As[32][136];   // [k][m], padded (136*4 % 8 == 0)
    __shared__ ull Bsd[32][64];                   // duplicated pairs (b,b)
    int tid = threadIdx.x;
    int m0 = blockIdx.y * 128, n0 = blockIdx.x * 64;
    // load A via float4 (row-major x2, transpose into [k][m])
    for (int i = tid; i < 128 * 8; i += 256) {
        int m = i >> 3, f = i & 7;
        int gm = m0 + m;
        float4 v = make_float4(0.f, 0.f, 0.f, 0.f);
        if (gm < N2) v = *(const float4*)(d_x2 + gm * 32 + f * 4);
        As[f * 4 + 0][m] = v.x;
        As[f * 4 + 1][m] = v.y;
        As[f * 4 + 2][m] = v.z;
        As[f * 4 + 3][m] = v.w;
    }
    for (int i = tid; i < 32 * 64; i += 256) {
        int k = i >> 6, n = i & 63;
        int j = n0 + n;
        int h = j >> 6, o = j & 63;
        float v = (h < 25) ? __ldg(w2b + h * 2048 + k * 64 + o)
                           : __ldg(b2b + k * 64 + o);
        Bsd[k][n] = pack_dup(v);
    }
    __syncthreads();
    int tx = tid & 15, ty = tid >> 4;   // tx: 4 n, ty: 4 m-pairs (8 m rows)
    ull acc[4][4];
#pragma unroll
    for (int mp = 0; mp < 4; mp++)
#pragma unroll
        for (int n = 0; n < 4; n++) acc[mp][n] = 0ull;
#pragma unroll
    for (int k = 0; k < 32; k++) {
        ull a2[4], bd[4];
#pragma unroll
        for (int mp = 0; mp < 4; mp++)
            a2[mp] = *(const ull*)&As[k][ty * 8 + mp * 2];
#pragma unroll
        for (int n = 0; n < 4; n++) bd[n] = Bsd[k][tx * 4 + n];
#pragma unroll
        for (int mp = 0; mp < 4; mp++)
#pragma unroll
            for (int n = 0; n < 4; n++)
                FMA2(acc[mp][n], a2[mp], bd[n], acc[mp][n]);
    }
#pragma unroll
    for (int mp = 0; mp < 4; mp++) {
        int gm = m0 + ty * 8 + mp * 2;
        if (gm < N2) {   // N2 even -> gm+1 < N2 too
#pragma unroll
            for (int n = 0; n < 4; n++) {
                unsigned int lo = (unsigned int)(acc[mp][n] & 0xffffffffull);
                unsigned int hi = (unsigned int)(acc[mp][n] >> 32);
                int col = n0 + tx * 4 + n;
                d_y[(size_t)gm * YW + col]       = __uint_as_float(lo);
                d_y[(size_t)(gm + 1) * YW + col] = __uint_as_float(hi);
            }
        }
    }
}

// ---------------- K7: layer-2 edge aggregation, CSR by source (block per node) ----------------
__global__ void __launch_bounds__(64) k_edge2csr() {
    int r = blockIdx.x;
    int deg = d_deg[r];
    if (deg == 0) return;
    __shared__ float Ys[YW];
    int tid = threadIdx.x;
    const float4* ysrc = (const float4*)(d_y + (size_t)r * YW);
    float4* ydst = (float4*)Ys;
#pragma unroll
    for (int i = tid; i < YW / 4; i += 64) ydst[i] = ysrc[i];
    __syncthreads();
    int off = d_off[r];
    for (int k = 0; k < deg; k++) {
        int slot = off + k;
        int c2 = d_edst[slot];
        const float* hp = d_hid + (size_t)slot * 25;
        float s = Ys[1600 + tid];
#pragma unroll
        for (int h = 0; h < 25; h++)
            s = fmaf(__ldg(hp + h), Ys[h * 64 + tid], s);
        atomicAdd(d_acc2 + c2 * 64 + tid, s);
    }
}

// ---------------- K8: fused layer-2 node update + pool2 + global mean scatter ----------------
__global__ void k_node2pool(const float* __restrict__ root2, const float* __restrict__ bias2,
                            const int* __restrict__ batch) {
    int idx = blockIdx.x * blockDim.x + threadIdx.x;
    if (idx >= N3 * 64) return;
    int q = idx >> 6, o = idx & 63;
    float v[2];
#pragma unroll
    for (int j = 0; j < 2; j++) {
        int c = 2 * q + j;
        float cnt = fmaxf((float)d_cnt2[c], 1.f);
        float t = d_acc2[c * 64 + o] / cnt + __ldg(bias2 + o);
#pragma unroll
        for (int i = 0; i < 32; i++)
            t = fmaf(d_x2[c * 32 + i], __ldg(root2 + i * 64 + o), t);
        v[j] = eluf(t);
    }
    float m = fmaxf(v[0], v[1]);
    int g = __ldg(batch + 4 * q);   // batch3[q] = batch[4q]
    atomicAdd(d_gsum + g * 64 + o, m);
    if (o == 0) atomicAdd(d_gcnt + g, 1);
}

// ---------------- K9: MLP head + log_softmax (one block per graph) ----------------
__global__ void k_head(const float* __restrict__ fc1_w, const float* __restrict__ fc1_b,
                       const float* __restrict__ fc2_w, const float* __restrict__ fc2_b,
                       float* __restrict__ out) {
    int g = blockIdx.x;
    int t = threadIdx.x;
    __shared__ float m[64];
    __shared__ float a[128];
    __shared__ float logits[10];
    if (t < 64)
        m[t] = d_gsum[g * 64 + t] / fmaxf((float)d_gcnt[g], 1.f);
    __syncthreads();
    float aj = __ldg(fc1_b + t);
#pragma unroll
    for (int i = 0; i < 64; i++)
        aj = fmaf(m[i], __ldg(fc1_w + i * 128 + t), aj);
    a[t] = eluf(aj);
    __syncthreads();
    if (t < 10) {
        float l = __ldg(fc2_b + t);
#pragma unroll 8
        for (int j = 0; j < 128; j++)
            l = fmaf(a[j], __ldg(fc2_w + j * 10 + t), l);
        logits[t] = l;
    }
    __syncthreads();
    if (t == 0) {
        float mx = -1e30f;
#pragma unroll
        for (int k = 0; k < 10; k++) mx = fmaxf(mx, logits[k]);
        float se = 0.f;
#pragma unroll
        for (int k = 0; k < 10; k++) se += expf(logits[k] - mx);
        float lse = logf(se) + mx;
#pragma unroll
        for (int k = 0; k < 10; k++) out[g * 10 + k] = logits[k] - lse;
    }
}

// ---------------- launcher ----------------
extern "C" void kernel_launch(void* const* d_in, const int* in_sizes, int n_in,
                              void* d_out, int out_size) {
    const float* x      = (const float*)d_in[0];
    const float* eattr  = (const float*)d_in[1];
    const float* pos    = (const float*)d_in[2];
    const float* w1a    = (const float*)d_in[3];
    const float* b1a    = (const float*)d_in[4];
    const float* w1b    = (const float*)d_in[5];
    const float* b1b    = (const float*)d_in[6];
    const float* root1  = (const float*)d_in[7];
    const float* bias1  = (const float*)d_in[8];
    const float* w2a    = (const float*)d_in[9];
    const float* b2a    = (const float*)d_in[10];
    const float* w2b    = (const float*)d_in[11];
    const float* b2b    = (const float*)d_in[12];
    const float* root2  = (const float*)d_in[13];
    const float* bias2  = (const float*)d_in[14];
    const float* fc1_w  = (const float*)d_in[15];
    const float* fc1_b  = (const float*)d_in[16];
    const float* fc2_w  = (const float*)d_in[17];
    const float* fc2_b  = (const float*)d_in[18];
    const int*   ei     = (const int*)d_in[19];
    const int*   batch  = (const int*)d_in[20];
    float* out = (float*)d_out;

    // one-time stream/event creation (not device memory; created outside capture
    // on the first (correctness) call, reused deterministically afterwards)
    static cudaStream_t s_side = nullptr;
    static cudaEvent_t ev_fork = nullptr, ev_join = nullptr;
    if (s_side == nullptr) {
        cudaStreamCreateWithFlags(&s_side, cudaStreamNonBlocking);
        cudaEventCreateWithFlags(&ev_fork, cudaEventDisableTiming);
        cudaEventCreateWithFlags(&ev_join, cudaEventDisableTiming);
    }

    k_zero<<<512, 256>>>();
    k_edge1<<<(EE * 32 + 255) / 256, 256>>>(x, eattr, w1a, b1a, w1b, b1b, ei);
    k_node1pool<<<(N2 * 32 + 255) / 256, 256>>>(x, root1, bias1, pos);

    // fork: side stream runs geom -> scan -> fill concurrently with ygemm
    cudaEventRecord(ev_fork, 0);
    cudaStreamWaitEvent(s_side, ev_fork, 0);

    {   // 4th kernel launch in program order -> gets profiled
        dim3 grid(YW / 64, (N2 + 127) / 128);
        k_ygemm<<<grid, 256>>>(w2b, b2b);
    }

    k_geom<<<(EE + 127) / 128, 128, 0, s_side>>>(ei);
    k_scan<<<1, 1024, 0, s_side>>>();
    k_fill<<<(EE + 127) / 128, 128, 0, s_side>>>(ei, w2a, b2a);

    cudaEventRecord(ev_join, s_side);
    cudaStreamWaitEvent(0, ev_join, 0);

    k_edge2csr<<<N2, 64>>>();
    k_node2pool<<<(N3 * 64 + 255) / 256, 256>>>(root2, bias2, batch);
    k_head<<<GG, 128>>>(fc1_w, fc1_b, fc2_w, fc2_b, out);
}

// round 5
// speedup vs baseline: 1.1028x; 1.1028x over previous
#include <cuda_runtime.h>
#include <cuda_bf16.h>
#include <math.h>
#include <stdint.h>

#define NN   30000
#define EE   120000
#define N2   15000
#define N3   7500
#define GG   512
#define YW   1664   // 26*64 = 13*128 (25 hidden rows + 1 bias row)

typedef unsigned long long ull;

#define FMA2(d, a, b, c) \
    asm("fma.rn.f32x2 %0, %1, %2, %3;" : "=l"(d) : "l"(a), "l"(b), "l"(c))

__device__ __forceinline__ ull pack_dup(float v) {
    ull p; unsigned int u = __float_as_uint(v);
    asm("mov.b64 %0, {%1, %1};" : "=l"(p) : "r"(u));
    return p;
}

// ---------------- scratch (static device allocations) ----------------
__device__ float d_acc1[NN * 32];
__device__ int   d_cnt1[NN];
__device__ float d_x2[N2 * 32];
__device__ float d_pos2[N2 * 2];
__device__ float d_cart[EE * 2];
__device__ int   d_maxbits;
__device__ float d_y[(size_t)N2 * YW];
__device__ float d_acc2[N2 * 64];
__device__ int   d_cnt2[N2];
__device__ float d_gsum[GG * 64];
__device__ int   d_gcnt[GG];
// CSR (edges grouped by layer-2 source node r2)
__device__ int   d_deg[N2];
__device__ int   d_off[N2];
__device__ int   d_cursor[N2];
__device__ int   d_edst[EE];
__device__ float d_hid[(size_t)EE * 25];

__device__ __forceinline__ float eluf(float x) { return x > 0.f ? x : expm1f(x); }

// ---------------- K0: zero accumulators ----------------
__global__ void k_zero() {
    int i = blockIdx.x * blockDim.x + threadIdx.x;
    int stride = gridDim.x * blockDim.x;
    for (int j = i; j < NN * 32; j += stride) d_acc1[j] = 0.f;
    for (int j = i; j < N2 * 64; j += stride) d_acc2[j] = 0.f;
    for (int j = i; j < NN; j += stride) d_cnt1[j] = 0;
    for (int j = i; j < N2; j += stride) { d_cnt2[j] = 0; d_deg[j] = 0; d_cursor[j] = 0; }
    for (int j = i; j < GG * 64; j += stride) d_gsum[j] = 0.f;
    for (int j = i; j < GG; j += stride) d_gcnt[j] = 0;
    if (i == 0) d_maxbits = 0;
}

// ---------------- K1: layer-1 edge kernel (warp per edge) ----------------
__global__ void k_edge1(const float* __restrict__ x, const float* __restrict__ ea,
                        const float* __restrict__ w1a, const float* __restrict__ b1a,
                        const float* __restrict__ w1b, const float* __restrict__ b1b,
                        const int* __restrict__ ei) {
    int warp = (blockIdx.x * blockDim.x + threadIdx.x) >> 5;
    int lane = threadIdx.x & 31;
    if (warp >= EE) return;
    int src = ei[warp];
    int dst = ei[EE + warp];
    float e0 = __ldg(ea + warp * 2);
    float e1 = __ldg(ea + warp * 2 + 1);
    float hid[25];
#pragma unroll
    for (int h = 0; h < 25; h++) {
        float v = fmaf(e0, __ldg(w1a + h), fmaf(e1, __ldg(w1a + 25 + h), __ldg(b1a + h)));
        hid[h] = fmaxf(v, 0.f);
    }
    float s = __ldg(b1b + lane);
#pragma unroll
    for (int h = 0; h < 25; h++)
        s = fmaf(hid[h], __ldg(w1b + h * 32 + lane), s);
    float xs = __ldg(x + src);
    atomicAdd(d_acc1 + dst * 32 + lane, xs * s);
    if (lane == 0) atomicAdd(d_cnt1 + dst, 1);
}

// ---------------- K2: fused layer-1 node update + pairwise max pool + pos mean ----------------
__global__ void k_node1pool(const float* __restrict__ x, const float* __restrict__ root1,
                            const float* __restrict__ bias1, const float* __restrict__ pos) {
    int idx = blockIdx.x * blockDim.x + threadIdx.x;
    if (idx >= N2 * 32) return;
    int p = idx >> 5, o = idx & 31;
    float v[2];
#pragma unroll
    for (int j = 0; j < 2; j++) {
        int n = 2 * p + j;
        float c = fmaxf((float)d_cnt1[n], 1.f);
        float t = d_acc1[n * 32 + o] / c + __ldg(x + n) * __ldg(root1 + o) + __ldg(bias1 + o);
        v[j] = eluf(t);
    }
    d_x2[idx] = fmaxf(v[0], v[1]);
    if (o < 2)
        d_pos2[p * 2 + o] = 0.5f * (pos[(2 * p) * 2 + o] + pos[(2 * p + 1) * 2 + o]);
}

// ---------------- K3 (4th launch, profiled): y GEMM 128x128 tile, 8x8/thread, FMA2 ----------------
// y[m, j] = sum_k x2[m,k] * B[k,j];  B[k, h*64+o] = w2b[h,k,o] (h<25) else b2b[k,o]
__global__ void __launch_bounds__(256) k_ygemm(const float* __restrict__ w2b,
                                               const float* __restrict__ b2b) {
    __shared__ __align__(16) float As[32][136];   // [k][m] padded (544B row, 16B aligned)
    __shared__ float Bs[32][128];                 // [k][n]
    int tid = threadIdx.x;
    int tx = tid & 15, ty = tid >> 4;             // tx -> n groups, ty -> m block
    int m0 = blockIdx.y * 128, n0 = blockIdx.x * 128;

    // load A (transpose 128 rows x 32 k via float4)
    for (int i = tid; i < 128 * 8; i += 256) {
        int m = i >> 3, f = i & 7;
        int gm = m0 + m;
        float4 v = make_float4(0.f, 0.f, 0.f, 0.f);
        if (gm < N2) v = *(const float4*)(d_x2 + gm * 32 + f * 4);
        As[f * 4 + 0][m] = v.x;
        As[f * 4 + 1][m] = v.y;
        As[f * 4 + 2][m] = v.z;
        As[f * 4 + 3][m] = v.w;
    }
    // load B: 32 k x 128 n
    for (int i = tid; i < 32 * 128; i += 256) {
        int k = i >> 7, n = i & 127;
        int j = n0 + n;
        int h = j >> 6, o = j & 63;
        Bs[k][n] = (h < 25) ? __ldg(w2b + h * 2048 + k * 64 + o)
                            : __ldg(b2b + k * 64 + o);
    }
    __syncthreads();

    ull acc[4][8];
#pragma unroll
    for (int p = 0; p < 4; p++)
#pragma unroll
        for (int j = 0; j < 8; j++) acc[p][j] = 0ull;

#pragma unroll
    for (int k = 0; k < 32; k++) {
        ull a2[4];
#pragma unroll
        for (int p = 0; p < 4; p++)
            a2[p] = *(const ull*)&As[k][ty * 8 + p * 2];
        ull bd[8];
#pragma unroll
        for (int j = 0; j < 8; j++)
            bd[j] = pack_dup(Bs[k][tx + 16 * j]);
#pragma unroll
        for (int p = 0; p < 4; p++)
#pragma unroll
            for (int j = 0; j < 8; j++)
                FMA2(acc[p][j], a2[p], bd[j], acc[p][j]);
    }

#pragma unroll
    for (int p = 0; p < 4; p++) {
        int gm = m0 + ty * 8 + p * 2;
        if (gm < N2) {   // N2 even -> gm+1 also valid
            float* r0 = d_y + (size_t)gm * YW + n0;
            float* r1 = r0 + YW;
#pragma unroll
            for (int j = 0; j < 8; j++) {
                unsigned int lo = (unsigned int)(acc[p][j] & 0xffffffffull);
                unsigned int hi = (unsigned int)(acc[p][j] >> 32);
                int n = tx + 16 * j;
                r0[n] = __uint_as_float(lo);
                r1[n] = __uint_as_float(hi);
            }
        }
    }
}

// ---------------- K4: edge geometry + abs-max + CSR degree + cnt2 ----------------
__global__ void k_geom(const int* __restrict__ ei) {
    int t = blockIdx.x * blockDim.x + threadIdx.x;
    float m = 0.f;
    if (t < EE) {
        int r2 = ei[t] >> 1, c2 = ei[EE + t] >> 1;
        float cx = 0.f, cy = 0.f;
        if (r2 != c2) {
            cx = d_pos2[c2 * 2]     - d_pos2[r2 * 2];
            cy = d_pos2[c2 * 2 + 1] - d_pos2[r2 * 2 + 1];
            atomicAdd(&d_deg[r2], 1);
            atomicAdd(&d_cnt2[c2], 1);
        }
        d_cart[t * 2] = cx;
        d_cart[t * 2 + 1] = cy;
        m = fmaxf(fabsf(cx), fabsf(cy));
    }
#pragma unroll
    for (int off = 16; off > 0; off >>= 1)
        m = fmaxf(m, __shfl_down_sync(0xffffffffu, m, off));
    if ((threadIdx.x & 31) == 0)
        atomicMax(&d_maxbits, __float_as_int(m));
}

// ---------------- K5: exclusive scan of degrees (single block) ----------------
__global__ void k_scan() {
    const int T = 1024;
    const int CH = (N2 + T - 1) / T;  // 15
    __shared__ int partial[T];
    int t = threadIdx.x;
    int base = t * CH;
    int local[CH];
    int s = 0;
#pragma unroll
    for (int i = 0; i < CH; i++) {
        int idx = base + i;
        int v = (idx < N2) ? d_deg[idx] : 0;
        local[i] = s;
        s += v;
    }
    partial[t] = s;
    __syncthreads();
    for (int d = 1; d < T; d <<= 1) {
        int v = (t >= d) ? partial[t - d] : 0;
        __syncthreads();
        partial[t] += v;
        __syncthreads();
    }
    int offset = (t > 0) ? partial[t - 1] : 0;
#pragma unroll
    for (int i = 0; i < CH; i++) {
        int idx = base + i;
        if (idx < N2) d_off[idx] = offset + local[i];
    }
}

// ---------------- K6: CSR fill + per-edge hidden MLP (relu) ----------------
__global__ void k_fill(const int* __restrict__ ei, const float* __restrict__ w2a,
                       const float* __restrict__ b2a) {
    int t = blockIdx.x * blockDim.x + threadIdx.x;
    if (t >= EE) return;
    int r2 = ei[t] >> 1, c2 = ei[EE + t] >> 1;
    if (r2 == c2) return;
    int pos = atomicAdd(&d_cursor[r2], 1);
    int slot = d_off[r2] + pos;
    d_edst[slot] = c2;
    float maxv = __int_as_float(d_maxbits);
    float inv = 0.5f / maxv;
    float ea0 = fmaf(d_cart[t * 2],     inv, 0.5f);
    float ea1 = fmaf(d_cart[t * 2 + 1], inv, 0.5f);
    float* hp = d_hid + (size_t)slot * 25;
#pragma unroll
    for (int h = 0; h < 25; h++) {
        float v = fmaf(ea0, __ldg(w2a + h), fmaf(ea1, __ldg(w2a + 25 + h), __ldg(b2a + h)));
        hp[h] = fmaxf(v, 0.f);
    }
}

// ---------------- K7: layer-2 edge aggregation, CSR by source ----------------
__global__ void __launch_bounds__(64) k_edge2csr() {
    int r = blockIdx.x;
    int deg = d_deg[r];
    if (deg == 0) return;
    __shared__ float Ys[YW];
    int tid = threadIdx.x;
    const float4* ysrc = (const float4*)(d_y + (size_t)r * YW);
    float4* ydst = (float4*)Ys;
#pragma unroll
    for (int i = tid; i < YW / 4; i += 64) ydst[i] = ysrc[i];
    __syncthreads();
    int off = d_off[r];
    for (int k = 0; k < deg; k++) {
        int slot = off + k;
        int c2 = d_edst[slot];
        const float* hp = d_hid + (size_t)slot * 25;
        float s = Ys[1600 + tid];
#pragma unroll
        for (int h = 0; h < 25; h++)
            s = fmaf(__ldg(hp + h), Ys[h * 64 + tid], s);
        atomicAdd(d_acc2 + c2 * 64 + tid, s);
    }
}

// ---------------- K8: fused layer-2 node update + pool2 + global mean scatter ----------------
__global__ void k_node2pool(const float* __restrict__ root2, const float* __restrict__ bias2,
                            const int* __restrict__ batch) {
    int idx = blockIdx.x * blockDim.x + threadIdx.x;
    if (idx >= N3 * 64) return;
    int q = idx >> 6, o = idx & 63;
    float v[2];
#pragma unroll
    for (int j = 0; j < 2; j++) {
        int c = 2 * q + j;
        float cnt = fmaxf((float)d_cnt2[c], 1.f);
        float t = d_acc2[c * 64 + o] / cnt + __ldg(bias2 + o);
#pragma unroll
        for (int i = 0; i < 32; i++)
            t = fmaf(d_x2[c * 32 + i], __ldg(root2 + i * 64 + o), t);
        v[j] = eluf(t);
    }
    float m = fmaxf(v[0], v[1]);
    int g = __ldg(batch + 4 * q);
    atomicAdd(d_gsum + g * 64 + o, m);
    if (o == 0) atomicAdd(d_gcnt + g, 1);
}

// ---------------- K9: MLP head + log_softmax (one block per graph) ----------------
__global__ void k_head(const float* __restrict__ fc1_w, const float* __restrict__ fc1_b,
                       const float* __restrict__ fc2_w, const float* __restrict__ fc2_b,
                       float* __restrict__ out) {
    int g = blockIdx.x;
    int t = threadIdx.x;
    __shared__ float m[64];
    __shared__ float a[128];
    __shared__ float logits[10];
    if (t < 64)
        m[t] = d_gsum[g * 64 + t] / fmaxf((float)d_gcnt[g], 1.f);
    __syncthreads();
    float aj = __ldg(fc1_b + t);
#pragma unroll
    for (int i = 0; i < 64; i++)
        aj = fmaf(m[i], __ldg(fc1_w + i * 128 + t), aj);
    a[t] = eluf(aj);
    __syncthreads();
    if (t < 10) {
        float l = __ldg(fc2_b + t);
#pragma unroll 8
        for (int j = 0; j < 128; j++)
            l = fmaf(a[j], __ldg(fc2_w + j * 10 + t), l);
        logits[t] = l;
    }
    __syncthreads();
    if (t == 0) {
        float mx = -1e30f;
#pragma unroll
        for (int k = 0; k < 10; k++) mx = fmaxf(mx, logits[k]);
        float se = 0.f;
#pragma unroll
        for (int k = 0; k < 10; k++) se += expf(logits[k] - mx);
        float lse = logf(se) + mx;
#pragma unroll
        for (int k = 0; k < 10; k++) out[g * 10 + k] = logits[k] - lse;
    }
}

// ---------------- launcher ----------------
extern "C" void kernel_launch(void* const* d_in, const int* in_sizes, int n_in,
                              void* d_out, int out_size) {
    const float* x      = (const float*)d_in[0];
    const float* eattr  = (const float*)d_in[1];
    const float* pos    = (const float*)d_in[2];
    const float* w1a    = (const float*)d_in[3];
    const float* b1a    = (const float*)d_in[4];
    const float* w1b    = (const float*)d_in[5];
    const float* b1b    = (const float*)d_in[6];
    const float* root1  = (const float*)d_in[7];
    const float* bias1  = (const float*)d_in[8];
    const float* w2a    = (const float*)d_in[9];
    const float* b2a    = (const float*)d_in[10];
    const float* w2b    = (const float*)d_in[11];
    const float* b2b    = (const float*)d_in[12];
    const float* root2  = (const float*)d_in[13];
    const float* bias2  = (const float*)d_in[14];
    const float* fc1_w  = (const float*)d_in[15];
    const float* fc1_b  = (const float*)d_in[16];
    const float* fc2_w  = (const float*)d_in[17];
    const float* fc2_b  = (const float*)d_in[18];
    const int*   ei     = (const int*)d_in[19];
    const int*   batch  = (const int*)d_in[20];
    float* out = (float*)d_out;

    k_zero<<<512, 256>>>();
    k_edge1<<<(EE * 32 + 255) / 256, 256>>>(x, eattr, w1a, b1a, w1b, b1b, ei);
    k_node1pool<<<(N2 * 32 + 255) / 256, 256>>>(x, root1, bias1, pos);
    {
        dim3 grid(YW / 128, (N2 + 127) / 128);   // 13 x 118, 4th launch -> profiled
        k_ygemm<<<grid, 256>>>(w2b, b2b);
    }
    k_geom<<<(EE + 255) / 256, 256>>>(ei);
    k_scan<<<1, 1024>>>();
    k_fill<<<(EE + 255) / 256, 256>>>(ei, w2a, b2a);
    k_edge2csr<<<N2, 64>>>();
    k_node2pool<<<(N3 * 64 + 255) / 256, 256>>>(root2, bias2, batch);
    k_head<<<GG, 128>>>(fc1_w, fc1_b, fc2_w, fc2_b, out);
}